// round 7
// baseline (speedup 1.0000x reference)
#include <cuda_runtime.h>
#include <math.h>

// ---------------- problem constants ----------------
#define NB    16
#define NCIN  20
#define NWID  64
#define NPIX  65536      // 256*256
#define NLAY  4
#define M1    16
#define M2    16
#define FCH   128
#define NCOUT 20

// ---------------- device scratch (no allocations allowed) ----------------
__device__ float  g_h0[NB*NWID*NPIX];          // 256 MB ping
__device__ float  g_h1[NB*NWID*NPIX];          // 256 MB pong
__device__ float2 g_T  [NB*NWID*256*16];       // fwd stage1: [b][i][h][ky]
__device__ float2 g_Xf [32*16*NB*NWID];        // fwd modes:  [kx][ky][b][i]
__device__ float2 g_Xo [NB*NWID*16*32];        // mixed:      [b][o][ky][kx]
__device__ float2 g_Z  [NB*NWID*256*16];       // inv stage1: [b][o][p][ky]
// twiddle tables
__device__ float g_cw[16*256], g_sw[16*256];   // cos/sin(2*pi*ky*w/256)  [ky][w]
__device__ float g_ch[32*256], g_sh[32*256];   // cos/sin(2*pi*kx*h/256)  [k][h], kx = k<16?k:224+k
__device__ float g_chT[256*32], g_shT[256*32]; // transposed [h][k]

// ---------------- table init (deterministic, cheap) ----------------
__global__ __launch_bounds__(256) void k_init_tables() {
    int id = blockIdx.x * 256 + threadIdx.x;    // 8192 threads
    if (id < 16*256) {
        int ky = id >> 8, w = id & 255;
        float s, c;
        sincospif((float)(ky * w) * (1.0f/128.0f), &s, &c);   // theta/pi = ky*w/128
        g_cw[id] = c; g_sw[id] = s;
    }
    if (id < 32*256) {
        int k = id >> 8, h = id & 255;
        int kx = (k < 16) ? k : (224 + k);      // rows 0..15 and 240..255
        float s, c;
        sincospif((float)(kx * h) * (1.0f/128.0f), &s, &c);
        g_ch[id] = c;        g_sh[id] = s;
        g_chT[h*32 + k] = c; g_shT[h*32 + k] = s;
    }
}

// ---------------- lift: h0[b,d,pix] = sum_c x[b,c,pix]*fc0_w[d,c] + fc0_b[d] ----------------
__global__ __launch_bounds__(256) void k_fc0(const float* __restrict__ x,
                                             const float* __restrict__ w,
                                             const float* __restrict__ bias) {
    __shared__ float ws[NWID*NCIN];
    __shared__ float bs[NWID];
    int t = threadIdx.x;
    for (int j = t; j < NWID*NCIN; j += 256) ws[j] = w[j];
    if (t < NWID) bs[t] = bias[t];
    __syncthreads();

    int idx = blockIdx.x * 256 + t;             // 1,048,576 pixels total
    int b = idx >> 16, pix = idx & 65535;
    float xin[NCIN];
#pragma unroll
    for (int c = 0; c < NCIN; c++) xin[c] = x[(size_t)(b*NCIN + c)*NPIX + pix];
#pragma unroll 4
    for (int d = 0; d < NWID; d++) {
        float acc = bs[d];
#pragma unroll
        for (int c = 0; c < NCIN; c++) acc = fmaf(xin[c], ws[d*NCIN + c], acc);
        g_h0[(size_t)(b*NWID + d)*NPIX + pix] = acc;
    }
}

// ---------------- forward DFT over W (radix-2 folded): ----------------
// X[ky] = sum_{w<128} (x[w] + (-1)^ky x[w+128]) e^{-2pi i ky w/256}
__global__ __launch_bounds__(256) void k_dftw(int srcsel) {
    const float* __restrict__ hin = srcsel ? g_h1 : g_h0;
    __shared__ float scw[16*128], ssw[16*128];     // 8 KB + 8 KB, w<128 only
    int t = threadIdx.x;
    for (int j = t; j < 2048; j += 256) {
        int ky = j >> 7, w = j & 127;
        scw[j] = g_cw[ky*256 + w];
        ssw[j] = g_sw[ky*256 + w];
    }
    __syncthreads();

    int lane = t & 31, warp = t >> 5;
    size_t row = (size_t)blockIdx.x * 8 + warp;    // 262,144 rows = B*WID*256
    const float* src = hin + row * 256;
    float xv[8];
#pragma unroll
    for (int j = 0; j < 8; j++) xv[j] = src[lane + 32*j];

    float A[4], Bv[4];
#pragma unroll
    for (int j = 0; j < 4; j++) { A[j] = xv[j] + xv[j+4]; Bv[j] = xv[j] - xv[j+4]; }

    float outv = 0.f;
#pragma unroll
    for (int ky = 0; ky < 16; ky++) {
        float cr = 0.f, ci = 0.f;
#pragma unroll
        for (int j = 0; j < 4; j++) {
            int w = lane + 32*j;                   // < 128
            float v = (ky & 1) ? Bv[j] : A[j];
            cr = fmaf( v, scw[ky*128 + w], cr);
            ci = fmaf(-v, ssw[ky*128 + w], ci);
        }
#pragma unroll
        for (int off = 16; off; off >>= 1) {       // xor-butterfly: ALL lanes end with the sum
            cr += __shfl_xor_sync(0xffffffffu, cr, off);
            ci += __shfl_xor_sync(0xffffffffu, ci, off);
        }
        // scatter: lane 2*ky keeps re, lane 2*ky+1 keeps im
        if (lane == 2*ky)     outv = cr;
        if (lane == 2*ky + 1) outv = ci;
    }
    // one coalesced 128B store per warp
    ((float*)(g_T + row*16))[lane] = outv;
}

// ---------------- forward DFT over H (twiddle rotation recurrence) ----------------
// Xf[kx,ky,b,i] = sum_h T[b,i,h,ky] * e^{-2pi i kx h/256}
__global__ __launch_bounds__(256) void k_dfth() {
    __shared__ float2 Ts[256*16];                  // [h][ky], 32 KB
    int bi = blockIdx.x;                           // b*64 + i  (1024 blocks)
    int t = threadIdx.x;
    {
        const float4* Tg4 = (const float4*)(g_T + (size_t)bi * 4096);
        float4* Ts4 = (float4*)Ts;
        for (int j = t; j < 2048; j += 256) Ts4[j] = Tg4[j];
    }
    __syncthreads();

    int kx  = t & 31;
    int ky  = t >> 5;                              // 0..7 ; thread also does ky+8
    int b = bi >> 6, i = bi & 63;

    // rotation step e^{-i theta kx}, theta = 2pi/256; track (c,s)=cos/sin(theta*kx*h)
    float c0 = g_chT[32 + kx], s0 = g_shT[32 + kx];
    float c = 1.f, s = 0.f;
    float re0 = 0.f, im0 = 0.f, re1 = 0.f, im1 = 0.f;
#pragma unroll 4
    for (int h = 0; h < 256; h++) {
        float2 a  = Ts[h*16 + ky];
        float2 bq = Ts[h*16 + ky + 8];
        re0 = fmaf(a.x,  c, fmaf( a.y,  s, re0));
        im0 = fmaf(a.y,  c, fmaf(-a.x,  s, im0));
        re1 = fmaf(bq.x, c, fmaf( bq.y, s, re1));
        im1 = fmaf(bq.y, c, fmaf(-bq.x, s, im1));
        float cn = fmaf(-s, s0, c*c0);
        float sn = fmaf( c, s0, s*c0);
        c = cn; s = sn;
    }
    g_Xf[((size_t)(kx*16 + ky    )*16 + b)*64 + i] = make_float2(re0, im0);
    g_Xf[((size_t)(kx*16 + ky + 8)*16 + b)*64 + i] = make_float2(re1, im1);
}

// ---------------- per-mode complex GEMM: Xo[b,o] = sum_i Xf[b,i] * W[i,o] ----------------
__global__ __launch_bounds__(256) void k_modemix(const float* __restrict__ w1r, const float* __restrict__ w1i,
                                                 const float* __restrict__ w2r, const float* __restrict__ w2i,
                                                 int layer) {
    __shared__ float2 Xs[16*64];                  // [b][i]   8 KB
    __shared__ float2 Ws[64*64];                  // [i][o]  32 KB
    int mode = blockIdx.x;                        // kx*16 + ky (512 blocks)
    int kx = mode >> 4, ky = mode & 15;
    int t = threadIdx.x;

    const float2* Xg = g_Xf + (size_t)mode * 1024;
    for (int j = t; j < 1024; j += 256) Xs[j] = Xg[j];

    const float* wr; const float* wi; int kxp;
    if (kx < 16) { wr = w1r; wi = w1i; kxp = kx; }
    else         { wr = w2r; wi = w2i; kxp = kx - 16; }
    size_t base = (size_t)layer * (NWID*NWID*256) + (size_t)kxp*16 + ky;
    for (int j = t; j < 4096; j += 256) {         // j = i*64 + o, elem stride 256
        Ws[j] = make_float2(wr[base + (size_t)j*256], wi[base + (size_t)j*256]);
    }
    __syncthreads();

#pragma unroll
    for (int r = 0; r < 4; r++) {
        int oid = t + 256*r;                      // b*64 + o
        int b = oid >> 6, o = oid & 63;
        float re = 0.f, im = 0.f;
#pragma unroll 8
        for (int i = 0; i < 64; i++) {
            float2 X = Xs[b*64 + i];
            float2 W = Ws[i*64 + o];
            re = fmaf(X.x, W.x, fmaf(-X.y, W.y, re));
            im = fmaf(X.x, W.y, fmaf( X.y, W.x, im));
        }
        g_Xo[((size_t)(b*64 + o)*16 + ky)*32 + kx] = make_float2(re, im);
    }
}

// ---------------- inverse DFT over H: Z[b,o,p,ky] = (1/65536) sum_kx Xo * e^{+2pi i kx p/256} ----------------
__global__ __launch_bounds__(256) void k_idfth() {
    __shared__ float2 Xs[16*32];                  // [ky][kx], 4 KB
    int bo = blockIdx.x;                          // b*64 + o (1024 blocks)
    int t = threadIdx.x;                          // p
    {
        const float4* Xg4 = (const float4*)(g_Xo + (size_t)bo * 512);
        float4* Xs4 = (float4*)Xs;
        for (int j = t; j < 256; j += 256) Xs4[j] = Xg4[j];
    }
    __syncthreads();

    float cth[32], sth[32];
#pragma unroll
    for (int k = 0; k < 32; k++) { cth[k] = g_ch[k*256 + t]; sth[k] = g_sh[k*256 + t]; }

    const float scale = 1.0f / 65536.0f;
#pragma unroll 2
    for (int ky = 0; ky < 16; ky++) {
        float re = 0.f, im = 0.f;
#pragma unroll
        for (int k = 0; k < 32; k++) {
            float2 X = Xs[ky*32 + k];
            re = fmaf(X.x, cth[k], fmaf(-X.y, sth[k], re));
            im = fmaf(X.x, sth[k], fmaf( X.y, cth[k], im));
        }
        g_Z[((size_t)bo*256 + t)*16 + ky] = make_float2(re*scale, im*scale);
    }
}

// ---------------- fused: irfft combine over W + 1x1 conv + bias (+GELU) ----------------
// o-outer / i-inner: weights read as float4 warp-broadcast LDS, hin kept in registers.
__global__ __launch_bounds__(256) void k_final(int srcsel,
                                               const float* __restrict__ pw_w,
                                               const float* __restrict__ pw_b,
                                               int layer, int apply_gelu) {
    const float* __restrict__ hin  = srcsel ? g_h1 : g_h0;
    float*       __restrict__ hout = srcsel ? g_h0 : g_h1;

    __shared__ float  pws[64*64];                 // [o][i] 16 KB (natural layout, i contiguous)
    __shared__ float2 Zs[64*16];                  // [o][ky] 8 KB, pre-scaled by (1 or 2)
    __shared__ float  pbs[64];

    int t = threadIdx.x;                          // w
    int bp = blockIdx.x;                          // b*256 + p (4096 blocks)
    int b = bp >> 8, p = bp & 255;

    const float* pwg = pw_w + (size_t)layer * 4096;
    for (int j = t; j < 4096; j += 256) pws[j] = pwg[j];
    if (t < 64) pbs[t] = pw_b[layer*64 + t];
    for (int j = t; j < 1024; j += 256) {         // j = o*16 + ky
        int o = j >> 4, ky = j & 15;
        float2 z = g_Z[((size_t)(b*64 + o)*256 + p)*16 + ky];
        float a = (ky == 0) ? 1.f : 2.f;          // hermitian double-count except ky=0
        Zs[j] = make_float2(a*z.x, a*z.y);
    }
    __syncthreads();

    float creg[16], sreg[16];
#pragma unroll
    for (int ky = 0; ky < 16; ky++) { creg[ky] = g_cw[ky*256 + t]; sreg[ky] = g_sw[ky*256 + t]; }

    size_t pixbase = (size_t)b * NWID * NPIX + (size_t)p * 256 + t;
    float hv[NWID];
#pragma unroll
    for (int i = 0; i < NWID; i++) hv[i] = hin[pixbase + (size_t)i * NPIX];

    size_t outbase = (size_t)b * NWID * NPIX + (size_t)p * 256 + t;
#pragma unroll 2
    for (int o = 0; o < 64; o++) {
        float s = pbs[o];
        const float4* w4 = (const float4*)(pws + o*64);
#pragma unroll
        for (int q = 0; q < 16; q++) {
            float4 w = w4[q];
            s = fmaf(hv[4*q+0], w.x, s);
            s = fmaf(hv[4*q+1], w.y, s);
            s = fmaf(hv[4*q+2], w.z, s);
            s = fmaf(hv[4*q+3], w.w, s);
        }
        // spectral combine: sum_ky a*(z.x*c - z.y*s)
        const float4* z4 = (const float4*)(Zs + o*16);
        float spec = 0.f;
#pragma unroll
        for (int k = 0; k < 8; k++) {
            float4 zz = z4[k];
            spec = fmaf(zz.x, creg[2*k],   fmaf(-zz.y, sreg[2*k],   spec));
            spec = fmaf(zz.z, creg[2*k+1], fmaf(-zz.w, sreg[2*k+1], spec));
        }
        float val = s + spec;
        if (apply_gelu) val = 0.5f * val * (1.f + erff(val * 0.70710678118654752f));
        hout[outbase + (size_t)o * NPIX] = val;
    }
}

// ---------------- fused projection: fc1 (64->128) + GELU + fc2 (128->20) ----------------
__global__ __launch_bounds__(256) void k_fc12(float* __restrict__ out,
                                              const float* __restrict__ fc1w, const float* __restrict__ fc1b,
                                              const float* __restrict__ fc2w, const float* __restrict__ fc2b) {
    __shared__ float w1s[FCH*NWID];               // [j][i] 32 KB, i contiguous
    __shared__ float w2t[FCH*NCOUT];              // [j][k] 10 KB (transposed), k contiguous
    __shared__ float b1s[FCH];
    __shared__ float b2s[NCOUT];
    int t = threadIdx.x;
    for (int j = t; j < FCH*NWID;  j += 256) w1s[j] = fc1w[j];
    for (int j = t; j < NCOUT*FCH; j += 256) {
        int k = j / FCH, jj = j % FCH;            // read coalesced over j
        w2t[jj*NCOUT + k] = fc2w[j];
    }
    if (t < FCH)   b1s[t] = fc1b[t];
    if (t < NCOUT) b2s[t] = fc2b[t];
    __syncthreads();

    int bp = blockIdx.x;                          // b*256 + p (4096 blocks)
    int b = bp >> 8, p = bp & 255;
    size_t pixbase = (size_t)b * NWID * NPIX + (size_t)p * 256 + t;

    float hv[NWID];
#pragma unroll
    for (int i = 0; i < NWID; i++) hv[i] = g_h0[pixbase + (size_t)i * NPIX];

    float acc[NCOUT];
#pragma unroll
    for (int k = 0; k < NCOUT; k++) acc[k] = b2s[k];

    for (int j = 0; j < FCH; j++) {
        float s = b1s[j];
        const float4* w4 = (const float4*)(w1s + j*NWID);
#pragma unroll
        for (int q = 0; q < 16; q++) {
            float4 w = w4[q];
            s = fmaf(hv[4*q+0], w.x, s);
            s = fmaf(hv[4*q+1], w.y, s);
            s = fmaf(hv[4*q+2], w.z, s);
            s = fmaf(hv[4*q+3], w.w, s);
        }
        s = 0.5f * s * (1.f + erff(s * 0.70710678118654752f));
        const float4* v4 = (const float4*)(w2t + j*NCOUT);  // 20 floats = 5 float4, 16B aligned (80B stride)
#pragma unroll
        for (int q = 0; q < 5; q++) {
            float4 w = v4[q];
            acc[4*q+0] = fmaf(s, w.x, acc[4*q+0]);
            acc[4*q+1] = fmaf(s, w.y, acc[4*q+1]);
            acc[4*q+2] = fmaf(s, w.z, acc[4*q+2]);
            acc[4*q+3] = fmaf(s, w.w, acc[4*q+3]);
        }
    }
#pragma unroll
    for (int k = 0; k < NCOUT; k++)
        out[(size_t)(b*NCOUT + k)*NPIX + (size_t)p*256 + t] = acc[k];
}

// ---------------- launch ----------------
extern "C" void kernel_launch(void* const* d_in, const int* in_sizes, int n_in,
                              void* d_out, int out_size) {
    const float* x    = (const float*)d_in[0];
    const float* w1r  = (const float*)d_in[1];
    const float* w1i  = (const float*)d_in[2];
    const float* w2r  = (const float*)d_in[3];
    const float* w2i  = (const float*)d_in[4];
    const float* pw_w = (const float*)d_in[5];
    const float* pw_b = (const float*)d_in[6];
    const float* fc0w = (const float*)d_in[7];
    const float* fc0b = (const float*)d_in[8];
    const float* fc1w = (const float*)d_in[9];
    const float* fc1b = (const float*)d_in[10];
    const float* fc2w = (const float*)d_in[11];
    const float* fc2b = (const float*)d_in[12];
    float* out = (float*)d_out;

    k_init_tables<<<32, 256>>>();
    k_fc0<<<4096, 256>>>(x, fc0w, fc0b);

    for (int l = 0; l < NLAY; l++) {
        int src = l & 1;                          // 0: read g_h0/write g_h1, 1: reverse
        k_dftw<<<32768, 256>>>(src);
        k_dfth<<<1024, 256>>>();
        k_modemix<<<512, 256>>>(w1r, w1i, w2r, w2i, l);
        k_idfth<<<1024, 256>>>();
        k_final<<<4096, 256>>>(src, pw_w, pw_b, l, (l < 3) ? 1 : 0);
    }
    // after l=3 (src=1), result lives in g_h0
    k_fc12<<<4096, 256>>>(out, fc1w, fc1b, fc2w, fc2b);
}

// round 8
// speedup vs baseline: 1.3739x; 1.3739x over previous
#include <cuda_runtime.h>
#include <math.h>

// ---------------- problem constants ----------------
#define NB    16
#define NCIN  20
#define NWID  64
#define NPIX  65536      // 256*256
#define NLAY  4
#define M1    16
#define M2    16
#define FCH   128
#define NCOUT 20

typedef unsigned long long ull;

// ---- packed f32x2 helpers (FFMA2: 2 MACs per issued instruction) ----
__device__ __forceinline__ ull ffma2(ull a, ull b, ull c) {
    ull d; asm("fma.rn.f32x2 %0, %1, %2, %3;" : "=l"(d) : "l"(a), "l"(b), "l"(c)); return d;
}
__device__ __forceinline__ ull add2(ull a, ull b) {
    ull d; asm("add.rn.f32x2 %0, %1, %2;" : "=l"(d) : "l"(a), "l"(b)); return d;
}
__device__ __forceinline__ ull pk2(float lo, float hi) {
    ull r; asm("mov.b64 %0, {%1,%2};" : "=l"(r) : "f"(lo), "f"(hi)); return r;
}
__device__ __forceinline__ float2 up2(ull v) {
    float2 r; asm("mov.b64 {%0,%1}, %2;" : "=f"(r.x), "=f"(r.y) : "l"(v)); return r;
}

// ---------------- device scratch (no allocations allowed) ----------------
__device__ float  g_h0[NB*NWID*NPIX];          // 256 MB ping
__device__ float  g_h1[NB*NWID*NPIX];          // 256 MB pong
__device__ float2 g_T  [NB*NWID*16*256];       // fwd stage1: [b][i][ky][h]   (layout changed!)
__device__ float2 g_Xf [32*16*NB*NWID];        // fwd modes:  [kx][ky][b][i]
__device__ float2 g_Xo [NB*NWID*16*32];        // mixed:      [b][o][ky][kx]
__device__ float2 g_Z  [NB*NWID*256*16];       // inv stage1: [b][o][p][ky]
// twiddle tables
__device__ float g_cw[16*256], g_sw[16*256];   // cos/sin(2*pi*ky*w/256)  [ky][w]
__device__ float g_ch[32*256], g_sh[32*256];   // cos/sin(2*pi*kx*h/256)  [k][h], kx = k<16?k:224+k
__device__ float g_chT[256*32], g_shT[256*32]; // transposed [h][k]
// packed DFT-W twiddles: col<16 = even ky (re/im pairs), col>=16 = odd ky
__device__ float g_E[32*128];                  // [col][w<128]

// ---------------- table init (deterministic, cheap) ----------------
__global__ __launch_bounds__(256) void k_init_tables() {
    int id = blockIdx.x * 256 + threadIdx.x;    // 8192 threads
    if (id < 16*256) {
        int ky = id >> 8, w = id & 255;
        float s, c;
        sincospif((float)(ky * w) * (1.0f/128.0f), &s, &c);
        g_cw[id] = c; g_sw[id] = s;
    }
    if (id < 32*256) {
        int k = id >> 8, h = id & 255;
        int kx = (k < 16) ? k : (224 + k);      // rows 0..15 and 240..255
        float s, c;
        sincospif((float)(kx * h) * (1.0f/128.0f), &s, &c);
        g_ch[id] = c;        g_sh[id] = s;
        g_chT[h*32 + k] = c; g_shT[h*32 + k] = s;
    }
    if (id < 32*128) {
        int c = id >> 7, w = id & 127;
        int ky = (c < 16) ? ((c >> 1) << 1) : (((((c - 16) >> 1)) << 1) + 1);
        int comp = c & 1;
        float s, cv;
        sincospif((float)(ky * w) * (1.0f/128.0f), &s, &cv);
        g_E[id] = comp ? -s : cv;               // re: cos, im: -sin
    }
}

// ---------------- lift: h0[b,d,pix] = sum_c x[b,c,pix]*fc0_w[d,c] + fc0_b[d] ----------------
__global__ __launch_bounds__(256) void k_fc0(const float* __restrict__ x,
                                             const float* __restrict__ w,
                                             const float* __restrict__ bias) {
    __shared__ float ws[NWID*NCIN];             // [d][c], 80B row stride (16B aligned)
    __shared__ float bs[NWID];
    int t = threadIdx.x;
    for (int j = t; j < NWID*NCIN; j += 256) ws[j] = w[j];
    if (t < NWID) bs[t] = bias[t];
    __syncthreads();

    int idx = blockIdx.x * 256 + t;
    int b = idx >> 16, pix = idx & 65535;
    ull xin2[10];
#pragma unroll
    for (int q = 0; q < 10; q++) {
        float x0 = x[(size_t)(b*NCIN + 2*q    )*NPIX + pix];
        float x1 = x[(size_t)(b*NCIN + 2*q + 1)*NPIX + pix];
        xin2[q] = pk2(x0, x1);
    }
#pragma unroll 4
    for (int d = 0; d < NWID; d++) {
        const ulonglong2* wp = (const ulonglong2*)(ws + d*NCIN);  // 20 floats = 5 x 16B
        ull a0 = 0ULL, a1 = 0ULL;
#pragma unroll
        for (int q = 0; q < 5; q++) {
            ulonglong2 ww = wp[q];
            a0 = ffma2(xin2[2*q],   ww.x, a0);
            a1 = ffma2(xin2[2*q+1], ww.y, a1);
        }
        float2 u = up2(add2(a0, a1));
        g_h0[(size_t)(b*NWID + d)*NPIX + pix] = u.x + u.y + bs[d];
    }
}

// ---------------- forward DFT over W (radix-2 fold + FMA2-over-w GEMM, shuffle-free) ----
// Block: 16 rows. Warp wg owns 4 output cols (cols 4wg..4wg+3); lane&15 = row,
// lane>>4 = w-half. One xor(16) shuffle combines halves.
__global__ __launch_bounds__(256) void k_dftw(int srcsel) {
    const float* __restrict__ hin = srcsel ? g_h1 : g_h0;
    __shared__ float Fs[16*276];                // A at +0 (128 w), B at +144; stride 276
    __shared__ float Es[32*136];                // [col][half*68 + wl]
    int t = threadIdx.x;
    int lane = t & 31, warp = t >> 5;

    // phase 1: warps 0..3 fold rows into Fs; warps 4..7 stage twiddles
    if (warp < 4) {
#pragma unroll
        for (int k = 0; k < 4; k++) {
            int r = warp * 4 + k;
            const float4* src4 = (const float4*)(hin + ((size_t)blockIdx.x * 16 + r) * 256);
            float4 lo = src4[lane], hi = src4[lane + 32];
            float4 A = make_float4(lo.x+hi.x, lo.y+hi.y, lo.z+hi.z, lo.w+hi.w);
            float4 B = make_float4(lo.x-hi.x, lo.y-hi.y, lo.z-hi.z, lo.w-hi.w);
            *(float4*)(Fs + r*276 +       lane*4) = A;
            *(float4*)(Fs + r*276 + 144 + lane*4) = B;
        }
    } else {
        int t2 = t - 128;
        for (int j = t2; j < 4096; j += 128) {
            int c = j >> 7, w = j & 127;
            Es[c*136 + (w >> 6)*68 + (w & 63)] = g_E[j];
        }
    }
    __syncthreads();

    // phase 2
    int rloc  = lane & 15;
    int whalf = lane >> 4;                       // 0: w 0..63, 1: w 64..127
    const float* vbase = Fs + rloc*276 + ((warp >= 4) ? 144 : 0) + whalf*64;
    const float* ebase = Es + (warp*4)*136 + whalf*68;

    ull acc[8];
#pragma unroll
    for (int q = 0; q < 8; q++) acc[q] = 0ULL;

#pragma unroll
    for (int it = 0; it < 16; it++) {
        int wl = it * 4;
        ulonglong2 v = *(const ulonglong2*)(vbase + wl);
#pragma unroll
        for (int c = 0; c < 4; c++) {
            ulonglong2 e = *(const ulonglong2*)(ebase + c*136 + wl);
            acc[2*c]   = ffma2(v.x, e.x, acc[2*c]);
            acc[2*c+1] = ffma2(v.y, e.y, acc[2*c+1]);
        }
    }

    float s[4];
#pragma unroll
    for (int c = 0; c < 4; c++) {
        float2 u = up2(add2(acc[2*c], acc[2*c+1]));
        float v = u.x + u.y;
        v += __shfl_xor_sync(0xffffffffu, v, 16);
        s[c] = v;
    }
    if (whalf == 0) {
        int bi = blockIdx.x >> 4;
        int h  = (blockIdx.x & 15) * 16 + rloc;
        int kyA = (warp < 4) ? 4*warp : 4*(warp - 4) + 1;
        g_T[(size_t)bi*4096 + (kyA    )*256 + h] = make_float2(s[0], s[1]);
        g_T[(size_t)bi*4096 + (kyA + 2)*256 + h] = make_float2(s[2], s[3]);
    }
}

// ---------------- forward DFT over H (twiddle rotation recurrence) ----------------
__global__ __launch_bounds__(256) void k_dfth() {
    __shared__ float2 Ts[16*256];                  // [ky][h], 32 KB
    int bi = blockIdx.x;                           // b*64 + i  (1024 blocks)
    int t = threadIdx.x;
    {
        const float4* Tg4 = (const float4*)(g_T + (size_t)bi * 4096);
        float4* Ts4 = (float4*)Ts;
        for (int j = t; j < 2048; j += 256) Ts4[j] = Tg4[j];
    }
    __syncthreads();

    int kx  = t & 31;
    int ky  = t >> 5;                              // 0..7 ; thread also does ky+8
    int b = bi >> 6, i = bi & 63;

    float c0 = g_chT[32 + kx], s0 = g_shT[32 + kx];
    float c = 1.f, s = 0.f;
    float re0 = 0.f, im0 = 0.f, re1 = 0.f, im1 = 0.f;
#pragma unroll 4
    for (int h = 0; h < 256; h++) {
        float2 a  = Ts[ky*256 + h];
        float2 bq = Ts[(ky + 8)*256 + h];
        re0 = fmaf(a.x,  c, fmaf( a.y,  s, re0));
        im0 = fmaf(a.y,  c, fmaf(-a.x,  s, im0));
        re1 = fmaf(bq.x, c, fmaf( bq.y, s, re1));
        im1 = fmaf(bq.y, c, fmaf(-bq.x, s, im1));
        float cn = fmaf(-s, s0, c*c0);
        float sn = fmaf( c, s0, s*c0);
        c = cn; s = sn;
    }
    g_Xf[((size_t)(kx*16 + ky    )*16 + b)*64 + i] = make_float2(re0, im0);
    g_Xf[((size_t)(kx*16 + ky + 8)*16 + b)*64 + i] = make_float2(re1, im1);
}

// ---------------- per-mode complex GEMM: Xo[b,o] = sum_i Xf[b,i] * W[i,o] ----------------
__global__ __launch_bounds__(256) void k_modemix(const float* __restrict__ w1r, const float* __restrict__ w1i,
                                                 const float* __restrict__ w2r, const float* __restrict__ w2i,
                                                 int layer) {
    __shared__ float2 Xs[16*64];                  // [b][i]   8 KB
    __shared__ float2 Ws[64*64];                  // [i][o]  32 KB
    int mode = blockIdx.x;                        // kx*16 + ky (512 blocks)
    int kx = mode >> 4, ky = mode & 15;
    int t = threadIdx.x;

    const float2* Xg = g_Xf + (size_t)mode * 1024;
    for (int j = t; j < 1024; j += 256) Xs[j] = Xg[j];

    const float* wr; const float* wi; int kxp;
    if (kx < 16) { wr = w1r; wi = w1i; kxp = kx; }
    else         { wr = w2r; wi = w2i; kxp = kx - 16; }
    size_t base = (size_t)layer * (NWID*NWID*256) + (size_t)kxp*16 + ky;
    for (int j = t; j < 4096; j += 256) {         // j = i*64 + o, elem stride 256
        Ws[j] = make_float2(wr[base + (size_t)j*256], wi[base + (size_t)j*256]);
    }
    __syncthreads();

#pragma unroll
    for (int r = 0; r < 4; r++) {
        int oid = t + 256*r;                      // b*64 + o
        int b = oid >> 6, o = oid & 63;
        float re = 0.f, im = 0.f;
#pragma unroll 8
        for (int i = 0; i < 64; i++) {
            float2 X = Xs[b*64 + i];
            float2 W = Ws[i*64 + o];
            re = fmaf(X.x, W.x, fmaf(-X.y, W.y, re));
            im = fmaf(X.x, W.y, fmaf( X.y, W.x, im));
        }
        g_Xo[((size_t)(b*64 + o)*16 + ky)*32 + kx] = make_float2(re, im);
    }
}

// ---------------- inverse DFT over H: Z[b,o,p,ky] = (1/65536) sum_kx Xo * e^{+2pi i kx p/256} ----------------
__global__ __launch_bounds__(256) void k_idfth() {
    __shared__ float2 Xs[16*32];                  // [ky][kx], 4 KB
    int bo = blockIdx.x;                          // b*64 + o (1024 blocks)
    int t = threadIdx.x;                          // p
    {
        const float4* Xg4 = (const float4*)(g_Xo + (size_t)bo * 512);
        float4* Xs4 = (float4*)Xs;
        for (int j = t; j < 256; j += 256) Xs4[j] = Xg4[j];
    }
    __syncthreads();

    float cth[32], sth[32];
#pragma unroll
    for (int k = 0; k < 32; k++) { cth[k] = g_ch[k*256 + t]; sth[k] = g_sh[k*256 + t]; }

    const float scale = 1.0f / 65536.0f;
#pragma unroll 2
    for (int ky = 0; ky < 16; ky++) {
        float re = 0.f, im = 0.f;
#pragma unroll
        for (int k = 0; k < 32; k++) {
            float2 X = Xs[ky*32 + k];
            re = fmaf(X.x, cth[k], fmaf(-X.y, sth[k], re));
            im = fmaf(X.x, sth[k], fmaf( X.y, cth[k], im));
        }
        g_Z[((size_t)bo*256 + t)*16 + ky] = make_float2(re*scale, im*scale);
    }
}

// ---------------- fused: irfft combine over W + 1x1 conv + bias (+GELU), FMA2 ----------------
__global__ __launch_bounds__(256) void k_final(int srcsel,
                                               const float* __restrict__ pw_w,
                                               const float* __restrict__ pw_b,
                                               int layer, int apply_gelu) {
    const float* __restrict__ hin  = srcsel ? g_h1 : g_h0;
    float*       __restrict__ hout = srcsel ? g_h0 : g_h1;

    __shared__ float  pws[64*64];                 // [o][i] 16 KB
    __shared__ float2 Zs[64*16];                  // [o][ky] 8 KB, hermitian pre-scaled
    __shared__ float  pbs[64];

    int t = threadIdx.x;                          // w
    int bp = blockIdx.x;                          // b*256 + p (4096 blocks)
    int b = bp >> 8, p = bp & 255;

    const float* pwg = pw_w + (size_t)layer * 4096;
    for (int j = t; j < 4096; j += 256) pws[j] = pwg[j];
    if (t < 64) pbs[t] = pw_b[layer*64 + t];
    for (int j = t; j < 1024; j += 256) {         // j = o*16 + ky
        int o = j >> 4, ky = j & 15;
        float2 z = g_Z[((size_t)(b*64 + o)*256 + p)*16 + ky];
        float a = (ky == 0) ? 1.f : 2.f;
        Zs[j] = make_float2(a*z.x, a*z.y);
    }
    __syncthreads();

    // packed twiddles (c, -s) per ky
    ull cs2[16];
#pragma unroll
    for (int ky = 0; ky < 16; ky++) cs2[ky] = pk2(g_cw[ky*256 + t], -g_sw[ky*256 + t]);

    // packed input pairs (hv[2q], hv[2q+1])
    size_t pixbase = (size_t)b * NWID * NPIX + (size_t)p * 256 + t;
    ull hv2[32];
#pragma unroll
    for (int q = 0; q < 32; q++) {
        float x0 = hin[pixbase + (size_t)(2*q    ) * NPIX];
        float x1 = hin[pixbase + (size_t)(2*q + 1) * NPIX];
        hv2[q] = pk2(x0, x1);
    }

#pragma unroll 2
    for (int o = 0; o < 64; o++) {
        const ulonglong2* w2 = (const ulonglong2*)(pws + o*64);
        ull a0 = 0ULL, a1 = 0ULL;
#pragma unroll
        for (int q = 0; q < 16; q++) {
            ulonglong2 ww = w2[q];
            a0 = ffma2(hv2[2*q],   ww.x, a0);
            a1 = ffma2(hv2[2*q+1], ww.y, a1);
        }
        const ulonglong2* z2 = (const ulonglong2*)(Zs + o*16);
        ull sp0 = 0ULL, sp1 = 0ULL;
#pragma unroll
        for (int q = 0; q < 8; q++) {
            ulonglong2 zz = z2[q];
            sp0 = ffma2(zz.x, cs2[2*q],   sp0);
            sp1 = ffma2(zz.y, cs2[2*q+1], sp1);
        }
        float2 u = up2(add2(add2(a0, a1), add2(sp0, sp1)));
        float val = u.x + u.y + pbs[o];
        if (apply_gelu) val = 0.5f * val * (1.f + erff(val * 0.70710678118654752f));
        hout[pixbase + (size_t)o * NPIX] = val;
    }
}

// ---------------- fused projection: fc1 (64->128) + GELU + fc2 (128->20), FMA2 ----------------
__global__ __launch_bounds__(256) void k_fc12(float* __restrict__ out,
                                              const float* __restrict__ fc1w, const float* __restrict__ fc1b,
                                              const float* __restrict__ fc2w, const float* __restrict__ fc2b) {
    __shared__ float w1s[FCH*NWID];               // [j][i] 32 KB
    __shared__ float w2t[FCH*NCOUT];              // [j][k] 10 KB (transposed), 80B rows
    __shared__ float b1s[FCH];
    __shared__ float b2s[NCOUT];
    int t = threadIdx.x;
    for (int j = t; j < FCH*NWID;  j += 256) w1s[j] = fc1w[j];
    for (int j = t; j < NCOUT*FCH; j += 256) {
        int k = j / FCH, jj = j % FCH;
        w2t[jj*NCOUT + k] = fc2w[j];
    }
    if (t < FCH)   b1s[t] = fc1b[t];
    if (t < NCOUT) b2s[t] = fc2b[t];
    __syncthreads();

    int bp = blockIdx.x;                          // b*256 + p (4096 blocks)
    int b = bp >> 8, p = bp & 255;
    size_t pixbase = (size_t)b * NWID * NPIX + (size_t)p * 256 + t;

    ull hv2[32];
#pragma unroll
    for (int q = 0; q < 32; q++) {
        float x0 = g_h0[pixbase + (size_t)(2*q    ) * NPIX];
        float x1 = g_h0[pixbase + (size_t)(2*q + 1) * NPIX];
        hv2[q] = pk2(x0, x1);
    }

    ull acc2[10];
#pragma unroll
    for (int q = 0; q < 10; q++) acc2[q] = pk2(b2s[2*q], b2s[2*q+1]);

    for (int j = 0; j < FCH; j++) {
        const ulonglong2* w2 = (const ulonglong2*)(w1s + j*NWID);
        ull a0 = 0ULL, a1 = 0ULL;
#pragma unroll
        for (int q = 0; q < 16; q++) {
            ulonglong2 ww = w2[q];
            a0 = ffma2(hv2[2*q],   ww.x, a0);
            a1 = ffma2(hv2[2*q+1], ww.y, a1);
        }
        float2 u = up2(add2(a0, a1));
        float s = u.x + u.y + b1s[j];
        s = 0.5f * s * (1.f + erff(s * 0.70710678118654752f));
        ull ss = pk2(s, s);
        const ulonglong2* v2 = (const ulonglong2*)(w2t + j*NCOUT);  // 20 floats = 5 x 16B
#pragma unroll
        for (int q = 0; q < 5; q++) {
            ulonglong2 ww = v2[q];
            acc2[2*q]   = ffma2(ss, ww.x, acc2[2*q]);
            acc2[2*q+1] = ffma2(ss, ww.y, acc2[2*q+1]);
        }
    }
#pragma unroll
    for (int q = 0; q < 10; q++) {
        float2 u = up2(acc2[q]);
        out[(size_t)(b*NCOUT + 2*q    )*NPIX + (size_t)p*256 + t] = u.x;
        out[(size_t)(b*NCOUT + 2*q + 1)*NPIX + (size_t)p*256 + t] = u.y;
    }
}

// ---------------- launch ----------------
extern "C" void kernel_launch(void* const* d_in, const int* in_sizes, int n_in,
                              void* d_out, int out_size) {
    const float* x    = (const float*)d_in[0];
    const float* w1r  = (const float*)d_in[1];
    const float* w1i  = (const float*)d_in[2];
    const float* w2r  = (const float*)d_in[3];
    const float* w2i  = (const float*)d_in[4];
    const float* pw_w = (const float*)d_in[5];
    const float* pw_b = (const float*)d_in[6];
    const float* fc0w = (const float*)d_in[7];
    const float* fc0b = (const float*)d_in[8];
    const float* fc1w = (const float*)d_in[9];
    const float* fc1b = (const float*)d_in[10];
    const float* fc2w = (const float*)d_in[11];
    const float* fc2b = (const float*)d_in[12];
    float* out = (float*)d_out;

    k_init_tables<<<32, 256>>>();
    k_fc0<<<4096, 256>>>(x, fc0w, fc0b);

    for (int l = 0; l < NLAY; l++) {
        int src = l & 1;                          // 0: read g_h0/write g_h1, 1: reverse
        k_dftw<<<16384, 256>>>(src);
        k_dfth<<<1024, 256>>>();
        k_modemix<<<512, 256>>>(w1r, w1i, w2r, w2i, l);
        k_idfth<<<1024, 256>>>();
        k_final<<<4096, 256>>>(src, pw_w, pw_b, l, (l < 3) ? 1 : 0);
    }
    // after l=3 (src=1), result lives in g_h0
    k_fc12<<<4096, 256>>>(out, fc1w, fc1b, fc2w, fc2b);
}